// round 13
// baseline (speedup 1.0000x reference)
#include <cuda_runtime.h>
#include <cuda_bf16.h>
#include <math.h>

#define NB    32
#define SL    20
#define DIM   256
#define BEAMW 4
#define G     128
#define NT    512
#define EPSC  1e-8f
#define LNEPS 1e-5f
#define NPOOL (NB * SL + 37 * NB * BEAMW)

// dynamic smem: A 64x72 bf16 (9216B) x2buf x hi/lo; B 64x136 bf16 (17408B) x2buf x hi/lo
#define OAH(b) ((b) * 9216)
#define OAL(b) (18432 + (b) * 9216)
#define OBH(b) (36864 + (b) * 17408)
#define OBL(b) (71680 + (b) * 17408)
#define SMEM_DYN 106496

// ---------------- static device scratch ----------------
__device__ float d_pool[NPOOL * DIM];
__device__ int   d_tab[2][NB * BEAMW][SL];
__device__ int   d_p[2][NB * BEAMW];
__device__ int   d_q[2][NB * BEAMW];
__device__ int   d_asrc[2][128 * 3];       // laster/last/cur: >=0 pool row, -1 start, -2 zero
__device__ float d_cpart[6 * 128 * 256];   // conv partials ks6 (K128 each)
__device__ float d_i1[4 * 128 * 1024];     // cell1 partials ks4 (K128 each)
__device__ float d_c2[8 * 128 * 1024];     // cell2 partials ks8 (K128 each)
__device__ float d_rs[128], d_ss[128];
__device__ float d_bscore[NB * BEAMW];
__device__ __nv_bfloat16 d_w1h[512 * 1024],  d_w1l[512 * 1024];
__device__ __nv_bfloat16 d_w2h[1024 * 1024], d_w2l[1024 * 1024];
__device__ __nv_bfloat16 d_wch[768 * 256],   d_wcl[768 * 256];
__device__ volatile unsigned g_flags[G];

// ---------------- one-hop flag-array grid barrier ----------------
__device__ __forceinline__ void gbar(unsigned& ep) {
    __syncthreads();
    int tid = threadIdx.x;
    if (tid == 0) {
        __threadfence();
        g_flags[blockIdx.x] = ep;
    }
    if (tid < G) {
        while (g_flags[tid] < ep) { }
    }
    __threadfence();
    __syncthreads();
    ep++;
}

// ---------------- helpers ----------------
__device__ __forceinline__ float geluf(float x) {
    return 0.5f * x * (1.0f + erff(x * 0.7071067811865476f));
}
__device__ __forceinline__ float sigmoidf_(float x) {
    return 1.0f / (1.0f + expf(-x));
}
__device__ __forceinline__ float halfReduceSum(float v, float* sbuf) {
    int tid = threadIdx.x;
    #pragma unroll
    for (int o = 16; o > 0; o >>= 1) v += __shfl_down_sync(0xffffffffu, v, o);
    if ((tid & 31) == 0) sbuf[tid >> 5] = v;
    __syncthreads();
    int h = tid >> 8;
    float r = 0.f;
    #pragma unroll
    for (int w = 0; w < 8; w++) r += sbuf[h * 8 + w];
    __syncthreads();
    return r;
}
__device__ __forceinline__ unsigned smem_u32(const void* p) {
    unsigned a;
    asm("{ .reg .u64 t; cvta.to.shared.u64 t, %1; cvt.u32.u64 %0, t; }" : "=r"(a) : "l"(p));
    return a;
}
__device__ __forceinline__ void cvt2(float a, float b, unsigned& h, unsigned& l) {
    __nv_bfloat162 hh = __floats2bfloat162_rn(a, b);
    __nv_bfloat162 ll = __floats2bfloat162_rn(a - __bfloat162float(hh.x),
                                              b - __bfloat162float(hh.y));
    h = *reinterpret_cast<unsigned*>(&hh);
    l = *reinterpret_cast<unsigned*>(&ll);
}

#define LDM_X4(r, addr) \
    asm volatile("ldmatrix.sync.aligned.m8n8.x4.shared.b16 {%0,%1,%2,%3}, [%4];" \
        : "=r"((r)[0]), "=r"((r)[1]), "=r"((r)[2]), "=r"((r)[3]) : "r"(addr))
#define LDM_X4T(r, addr) \
    asm volatile("ldmatrix.sync.aligned.m8n8.x4.trans.shared.b16 {%0,%1,%2,%3}, [%4];" \
        : "=r"((r)[0]), "=r"((r)[1]), "=r"((r)[2]), "=r"((r)[3]) : "r"(addr))
#define MMA16816(d, a, b0, b1) \
    asm volatile("mma.sync.aligned.m16n8k16.row.col.f32.bf16.bf16.f32 " \
        "{%0,%1,%2,%3},{%4,%5,%6,%7},{%8,%9},{%0,%1,%2,%3};" \
        : "+f"((d)[0]), "+f"((d)[1]), "+f"((d)[2]), "+f"((d)[3]) \
        : "r"((a)[0]), "r"((a)[1]), "r"((a)[2]), "r"((a)[3]), "r"(b0), "r"(b1))
#define CPA16(dst, src) \
    asm volatile("cp.async.cg.shared.global [%0], [%1], 16;" :: "r"(dst), "l"(src) : "memory")
#define CPA_COMMIT() asm volatile("cp.async.commit_group;" ::: "memory")
#define CPA_WAIT()   asm volatile("cp.async.wait_group 0;" ::: "memory")

// ---------------- pipelined mma GEMM job: 64 rows x 128 cols x K128 (2 chunks) ----
// amode 0: A rows from pool via dsc (seg = global K col >> 8); amode 1: A = gelu(sum 4 i1 slabs + gb).
// 16 warps: mg=w>>3 -> rows mg*32..+31 ; ng=w&7 -> cols ng*16..+15.
__device__ void gemm_mma(int amode, int ri, int kbase,
                         const int* __restrict__ dsc, const float* __restrict__ start,
                         const float* __restrict__ gb,
                         const __nv_bfloat16* __restrict__ bH,
                         const __nv_bfloat16* __restrict__ bL, int Nw, int coloff,
                         float* __restrict__ C, int ldc,
                         char* dsb, unsigned sbase) {
    int tid = threadIdx.x;
    int lane = tid & 31, w = tid >> 5;
    int mg = w >> 3, ng = w & 7;
    float acc[16];
    #pragma unroll
    for (int i = 0; i < 16; i++) acc[i] = 0.f;

    int r = tid >> 3;            // 0..63 (A staging row)
    int e8 = (tid & 7) * 8;      // 0..56 (A staging col slice)
    int m = ri * 64 + r;
    unsigned stA = (unsigned)(r * 72 + e8) * 2;
    unsigned aOff0 = ((mg * 32 + (lane & 15)) * 72 + (lane >> 4) * 8) * 2;
    unsigned aOff1 = ((mg * 32 + 16 + (lane & 15)) * 72 + (lane >> 4) * 8) * 2;
    unsigned bOff  = ((lane & 15) * 136 + ng * 16 + (lane >> 4) * 8) * 2;

    float x[8];
    auto loadA = [&](int c, float* xr) {
        int kcol = kbase + c * 64;
        if (amode == 0) {
            int seg = kcol >> 8;
            int cseg = (kcol & 255) + e8;
            int id = dsc[m * 3 + seg];
            if (id >= -1) {
                const float* s = (id >= 0) ? (d_pool + (size_t)id * 256 + cseg)
                                           : (start + cseg);
                float4 v0 = *(const float4*)s, v1 = *(const float4*)(s + 4);
                xr[0] = v0.x; xr[1] = v0.y; xr[2] = v0.z; xr[3] = v0.w;
                xr[4] = v1.x; xr[5] = v1.y; xr[6] = v1.z; xr[7] = v1.w;
            } else {
                #pragma unroll
                for (int j = 0; j < 8; j++) xr[j] = 0.f;
            }
        } else {
            int kt = kcol + e8;
            const float* pa = d_i1 + (size_t)m * 1024 + kt;
            float4 a0 = *(const float4*)pa,            a1 = *(const float4*)(pa + 4);
            float4 b0 = *(const float4*)(pa + 131072), b1 = *(const float4*)(pa + 131072 + 4);
            float4 c0 = *(const float4*)(pa + 262144), c1 = *(const float4*)(pa + 262144 + 4);
            float4 d0 = *(const float4*)(pa + 393216), d1 = *(const float4*)(pa + 393216 + 4);
            float4 g0 = *(const float4*)(gb + kt),     g1 = *(const float4*)(gb + kt + 4);
            xr[0] = geluf(a0.x + b0.x + c0.x + d0.x + g0.x);
            xr[1] = geluf(a0.y + b0.y + c0.y + d0.y + g0.y);
            xr[2] = geluf(a0.z + b0.z + c0.z + d0.z + g0.z);
            xr[3] = geluf(a0.w + b0.w + c0.w + d0.w + g0.w);
            xr[4] = geluf(a1.x + b1.x + c1.x + d1.x + g1.x);
            xr[5] = geluf(a1.y + b1.y + c1.y + d1.y + g1.y);
            xr[6] = geluf(a1.z + b1.z + c1.z + d1.z + g1.z);
            xr[7] = geluf(a1.w + b1.w + c1.w + d1.w + g1.w);
        }
    };
    auto storeA = [&](const float* xr, int b) {
        uint4 H, L;
        cvt2(xr[0], xr[1], H.x, L.x); cvt2(xr[2], xr[3], H.y, L.y);
        cvt2(xr[4], xr[5], H.z, L.z); cvt2(xr[6], xr[7], H.w, L.w);
        *(uint4*)(dsb + OAH(b) + stA) = H;
        *(uint4*)(dsb + OAL(b) + stA) = L;
    };
    auto cpB = [&](int c, int b) {
        int kt = kbase + c * 64;
        #pragma unroll
        for (int e = 0; e < 2; e++) {
            int idx = tid + 512 * e;
            int row = idx >> 4, c16 = idx & 15;
            size_t so = (size_t)(kt + row) * Nw + coloff + c16 * 8;
            unsigned off = (unsigned)(row * 136 + c16 * 8) * 2;
            CPA16(sbase + OBH(b) + off, bH + so);
            CPA16(sbase + OBL(b) + off, bL + so);
        }
    };

    loadA(0, x);
    cpB(0, 0);
    CPA_COMMIT();
    storeA(x, 0);
    CPA_WAIT();
    __syncthreads();

    int p = 0;
    #pragma unroll
    for (int c = 0; c < 2; c++) {
        float xn[8];
        if (c == 0) {
            loadA(1, xn);
            cpB(1, 1);
            CPA_COMMIT();
        }
        unsigned aH0 = sbase + OAH(p) + aOff0;
        unsigned aH1 = sbase + OAH(p) + aOff1;
        unsigned aL0 = sbase + OAL(p) + aOff0;
        unsigned aL1 = sbase + OAL(p) + aOff1;
        unsigned bHs = sbase + OBH(p) + bOff;
        unsigned bLs = sbase + OBL(p) + bOff;
        #pragma unroll
        for (int kk = 0; kk < 4; kk++) {
            unsigned ah0[4], ah1[4], al0[4], al1[4], bh[4], bl[4];
            LDM_X4(ah0, aH0 + kk * 32);
            LDM_X4(ah1, aH1 + kk * 32);
            LDM_X4(al0, aL0 + kk * 32);
            LDM_X4(al1, aL1 + kk * 32);
            LDM_X4T(bh, bHs + kk * 4352);
            LDM_X4T(bl, bLs + kk * 4352);
            MMA16816(acc,      ah0, bh[0], bh[1]);
            MMA16816(acc,      al0, bh[0], bh[1]);
            MMA16816(acc,      ah0, bl[0], bl[1]);
            MMA16816(acc + 4,  ah0, bh[2], bh[3]);
            MMA16816(acc + 4,  al0, bh[2], bh[3]);
            MMA16816(acc + 4,  ah0, bl[2], bl[3]);
            MMA16816(acc + 8,  ah1, bh[0], bh[1]);
            MMA16816(acc + 8,  al1, bh[0], bh[1]);
            MMA16816(acc + 8,  ah1, bl[0], bl[1]);
            MMA16816(acc + 12, ah1, bh[2], bh[3]);
            MMA16816(acc + 12, al1, bh[2], bh[3]);
            MMA16816(acc + 12, ah1, bl[2], bl[3]);
        }
        if (c == 0) {
            storeA(xn, 1);
            CPA_WAIT();
        }
        __syncthreads();
        p = 1;
    }

    int rw = mg * 32 + (lane >> 2);
    int cw = ng * 16 + (lane & 3) * 2;
    *(float2*)(C + (size_t)rw * ldc + cw)            = make_float2(acc[0], acc[1]);
    *(float2*)(C + (size_t)(rw + 8) * ldc + cw)      = make_float2(acc[2], acc[3]);
    *(float2*)(C + (size_t)rw * ldc + cw + 8)        = make_float2(acc[4], acc[5]);
    *(float2*)(C + (size_t)(rw + 8) * ldc + cw + 8)  = make_float2(acc[6], acc[7]);
    *(float2*)(C + (size_t)(rw + 16) * ldc + cw)     = make_float2(acc[8], acc[9]);
    *(float2*)(C + (size_t)(rw + 24) * ldc + cw)     = make_float2(acc[10], acc[11]);
    *(float2*)(C + (size_t)(rw + 16) * ldc + cw + 8) = make_float2(acc[12], acc[13]);
    *(float2*)(C + (size_t)(rw + 24) * ldc + cw + 8) = make_float2(acc[14], acc[15]);
}

// ---------------- the persistent mega kernel ----------------
__global__ void __launch_bounds__(NT, 1)
mega(const float* __restrict__ sequence, const float* __restrict__ input_mask,
     const float* __restrict__ w_init, const float* __restrict__ b_init,
     const float* __restrict__ ln1_g, const float* __restrict__ ln1_b,
     const float* __restrict__ scorer_w, const float* __restrict__ scorer_b,
     const float* __restrict__ conv_w, const float* __restrict__ conv_b,
     const float* __restrict__ start,
     const float* __restrict__ wcell1_w, const float* __restrict__ wcell1_b,
     const float* __restrict__ wcell2_w, const float* __restrict__ wcell2_b,
     const float* __restrict__ ln2_g, const float* __restrict__ ln2_b,
     float* __restrict__ out) {
    extern __shared__ char dsb[];
    unsigned sbase = smem_u32(dsb);
    __shared__ float sred[16];
    __shared__ int   sparK[BEAMW], swrpos[BEAMW], swrval[BEAMW];

    int tid = threadIdx.x;
    int bid = blockIdx.x;
    int h   = tid >> 8;
    int col = tid & 255;
    unsigned ep = 1;

    // ---- init 0: elementwise weight conversion to bf16 hi/lo ----
    {
        const int T1 = 512 * 1024, T2 = T1 + 1024 * 1024, T3 = T2 + 768 * 256;
        for (int idx = bid * NT + tid; idx < T3; idx += G * NT) {
            float v; __nv_bfloat16* ph; __nv_bfloat16* pl; int o;
            if (idx < T1)      { v = wcell1_w[idx];      ph = d_w1h; pl = d_w1l; o = idx; }
            else if (idx < T2) { o = idx - T1; v = wcell2_w[o]; ph = d_w2h; pl = d_w2l; }
            else               { o = idx - T2; v = conv_w[o];   ph = d_wch; pl = d_wcl; }
            __nv_bfloat16 hh = __float2bfloat16(v);
            ph[o] = hh;
            pl[o] = __float2bfloat16(v - __bfloat162float(hh));
        }
    }
    // ---- init 1: pool tokens = LN1(sequence @ w_init + b_init); 2 rows/block ----
    {
        float* sX = (float*)dsb;
        for (int job = bid; job < (NB * SL) / 2; job += G) {
            int row = job * 2 + h;
            sX[h * 256 + col] = sequence[(size_t)row * DIM + col];
            __syncthreads();
            float acc = 0.f;
            for (int i = 0; i < DIM; i++)
                acc += sX[h * 256 + i] * w_init[i * DIM + col];
            float y = acc + b_init[col];
            float s1 = halfReduceSum(y, sred);
            float s2 = halfReduceSum(y * y, sred);
            float m = s1 * (1.0f / DIM);
            float var = s2 * (1.0f / DIM) - m * m;
            d_pool[(size_t)row * DIM + col] =
                (y - m) * rsqrtf(var + LNEPS) * ln1_g[col] + ln1_b[col];
            __syncthreads();
        }
        if (bid == G - 1 && tid < 768) { d_asrc[0][tid] = 0; d_asrc[1][tid] = 0; }
    }
    gbar(ep);

    // ---- init 2: stack tables + first descriptors (K=1) ----
    if (bid < NB && tid == 0) {
        int n = bid;
        d_tab[0][n * BEAMW][0] = n * SL + 0;
        d_tab[0][n * BEAMW][1] = n * SL + 1;
        int p = (input_mask[n * SL + 1] > 0.5f) ? 1 : 0;
        d_p[0][n * BEAMW] = p;
        d_q[0][n * BEAMW] = 0;
        d_asrc[0][n * 3 + 0] = (p >= 1) ? (n * SL + 0) : -1;
        d_asrc[0][n * 3 + 1] = n * SL + p;
        d_asrc[0][n * 3 + 2] = n * SL + 2;
    }
    gbar(ep);

    int K = 1, buf = 0;
    for (int t = 2; t <= 2 * SL - 2; t++) {
        int newK = (2 * K < BEAMW) ? 2 * K : BEAMW;
        int nb2 = buf ^ 1;
        const int* dsc = d_asrc[buf];

        // ---- P1: cell1 (ks4: 64 jobs) + conv (ks6: 24 jobs), K128 each ----
        if (bid < 88) {
            if (bid < 64) {
                int ks = bid & 3, ct = (bid >> 2) & 7, ri = bid >> 5;
                gemm_mma(0, ri, ks * 128, dsc, start, nullptr,
                         d_w1h, d_w1l, 1024, ct * 128,
                         d_i1 + (size_t)ks * 131072 + (size_t)ri * 64 * 1024 + ct * 128,
                         1024, dsb, sbase);
            } else {
                int j = bid - 64;
                int ks = j % 6, r2 = j / 6;
                int ct = r2 & 1, ri = r2 >> 1;
                gemm_mma(0, ri, ks * 128, dsc, start, nullptr,
                         d_wch, d_wcl, 256, ct * 128,
                         d_cpart + (size_t)ks * 32768 + (size_t)ri * 64 * 256 + ct * 128,
                         256, dsb, sbase);
            }
        }
        gbar(ep);

        // ---- P2: cell2 (ks8: 128 jobs, K128) + distributed scores tail ----
        {
            int ks = bid & 7, ct = (bid >> 3) & 7, ri = bid >> 6;
            gemm_mma(1, ri, ks * 128, nullptr, nullptr, wcell1_b,
                     d_w2h, d_w2l, 1024, ct * 128,
                     d_c2 + (size_t)ks * 131072 + (size_t)ri * 64 * 1024 + ct * 128,
                     1024, dsb, sbase);
        }
        if (bid < 64) {
            int m = 2 * bid + h;
            int valid = (m < NB * K);
            int mm = valid ? m : 0;
            float s = 0.f;
            #pragma unroll
            for (int ks = 0; ks < 6; ks++)
                s += d_cpart[ks * 32768 + mm * 256 + col];
            float y = valid ? geluf(s + conv_b[col]) * scorer_w[col] : 0.f;
            float dot = halfReduceSum(y, sred);
            if (col == 0 && valid) {
                int n = mm / K, k = mm % K;
                float dec = sigmoidf_(dot + scorer_b[0]);
                int p = d_p[buf][n * BEAMW + k];
                int q = d_q[buf][n * BEAMW + k];
                float lp  = (p >= 1) ? 1.0f : 0.0f;
                float cmf = (q < SL - 2) ? input_mask[n * SL + 2 + q] : 0.0f;
                float bz  = ((lp == 0.0f) && (cmf == 0.0f)) ? 1.0f : 0.0f;
                float rs = cmf * dec + (1.0f - cmf);
                rs = lp * rs; rs = bz + (1.0f - bz) * rs; rs = logf(rs + EPSC);
                float ss = lp * (1.0f - dec) + (1.0f - lp);
                ss = cmf * ss; ss = (1.0f - bz) * ss; ss = logf(ss + EPSC);
                d_rs[mm] = rs;
                d_ss[mm] = ss;
            }
        }
        gbar(ep);

        // ---- P3: top-k + tables + descriptors (blocks 0-31) || compose (0-63) ----
        if (bid < NB) {
            int n = bid;
            if (tid == 0) {
                int C2 = 2 * K;
                float sc[8];
                for (int c = 0; c < C2; c++)
                    sc[c] = (c < K) ? d_rs[n * K + c] : d_ss[n * K + (c - K)];
                int sel[BEAMW];
                if (C2 <= BEAMW) {
                    for (int s2 = 0; s2 < C2; s2++) { sel[s2] = s2; d_bscore[n * BEAMW + s2] = sc[s2]; }
                } else {
                    bool used[8];
                    for (int c = 0; c < C2; c++) used[c] = false;
                    for (int s2 = 0; s2 < BEAMW; s2++) {
                        int best = -1; float bv = 0.f;
                        for (int c = 0; c < C2; c++) {
                            if (used[c]) continue;
                            if (best < 0 || sc[c] > bv) { best = c; bv = sc[c]; }
                        }
                        used[best] = true; sel[s2] = best;
                        d_bscore[n * BEAMW + s2] = bv;
                    }
                }
                for (int s2 = 0; s2 < newK; s2++) {
                    int c = sel[s2];
                    int isred = (c < K);
                    int k = isred ? c : (c - K);
                    int p = d_p[buf][n * BEAMW + k];
                    int q = d_q[buf][n * BEAMW + k];
                    int lp = (p >= 1);
                    float cmf = (q < SL - 2) ? input_mask[n * SL + 2 + q] : 0.0f;
                    int cm = (cmf > 0.5f);
                    int wr_pos = -1, newp = p, newq = q, wr_val = 0;
                    if (isred) {
                        if (lp) { wr_pos = p - 1; newp = p - 1;
                                  wr_val = NB * SL + (t - 2) * (NB * BEAMW) + n * BEAMW + k; }
                    } else {
                        newq = q + 1;
                        if (cm) { wr_pos = p + 1; newp = p + 1; wr_val = n * SL + 2 + q; }
                    }
                    sparK[s2] = k; swrpos[s2] = wr_pos; swrval[s2] = wr_val;
                    d_p[nb2][n * BEAMW + s2] = newp;
                    d_q[nb2][n * BEAMW + s2] = newq;
                    const int* ot = d_tab[buf][n * BEAMW + k];
                    int laster = -1;
                    if (newp >= 1) {
                        int d = newp - 1;
                        laster = (d == wr_pos) ? wr_val : ot[d];
                    }
                    int lastv = (newp == wr_pos) ? wr_val : ot[newp];
                    int curv  = (newq < SL - 2) ? (n * SL + 2 + newq) : -2;
                    int m2 = n * newK + s2;
                    d_asrc[nb2][m2 * 3 + 0] = laster;
                    d_asrc[nb2][m2 * 3 + 1] = lastv;
                    d_asrc[nb2][m2 * 3 + 2] = curv;
                }
            }
            __syncthreads();
            if (tid < newK * SL) {
                int s2 = tid / SL, d = tid % SL;
                int pk = sparK[s2];
                int v = d_tab[buf][n * BEAMW + pk][d];
                if (d == swrpos[s2]) v = swrval[s2];
                d_tab[nb2][n * BEAMW + s2][d] = v;
            }
            __syncthreads();
        }
        if (bid < 64) {
            int m = 2 * bid + h;
            int valid = (m < NB * K);
            int mm = valid ? m : 0;
            float seg[4];
            #pragma unroll
            for (int sg = 0; sg < 4; sg++) {
                float v = wcell2_b[sg * 256 + col];
                #pragma unroll
                for (int ks = 0; ks < 8; ks++)
                    v += d_c2[ks * 131072 + (size_t)mm * 1024 + sg * 256 + col];
                seg[sg] = v;
            }
            int id1 = dsc[mm * 3 + 0];
            int id2 = dsc[mm * 3 + 1];
            float c1 = (id1 >= 0) ? d_pool[(size_t)id1 * DIM + col] : start[col];
            float c2v = d_pool[(size_t)id2 * DIM + col];
            float x = sigmoidf_(seg[0]) * c1
                    + sigmoidf_(seg[1]) * c2v
                    + sigmoidf_(seg[2]) * seg[3];
            float xm = valid ? x : 0.f;
            float s1 = halfReduceSum(xm, sred);
            float s2 = halfReduceSum(xm * xm, sred);
            if (valid) {
                float mn = s1 * (1.0f / DIM);
                float var = s2 * (1.0f / DIM) - mn * mn;
                int n = mm / K, k = mm % K;
                int rid = NB * SL + (t - 2) * (NB * BEAMW) + n * BEAMW + k;
                d_pool[(size_t)rid * DIM + col] =
                    (x - mn) * rsqrtf(var + LNEPS) * ln2_g[col] + ln2_b[col];
            }
        }
        gbar(ep);
        buf ^= 1;
        K = newK;
    }

    // ---- final: softmax over beam scores, weighted top-of-stack sum ----
    if (bid < NB && h == 0) {
        int n = bid;
        float sc[BEAMW];
        float mx = -1e30f;
        #pragma unroll
        for (int k = 0; k < BEAMW; k++) { sc[k] = d_bscore[n * BEAMW + k]; mx = fmaxf(mx, sc[k]); }
        float e[BEAMW], sum = 0.f;
        #pragma unroll
        for (int k = 0; k < BEAMW; k++) { e[k] = expf(sc[k] - mx); sum += e[k]; }
        float o = 0.f;
        #pragma unroll
        for (int k = 0; k < BEAMW; k++) {
            int p = d_p[buf][n * BEAMW + k];
            int slot = d_tab[buf][n * BEAMW + k][p];
            o += (e[k] / sum) * d_pool[(size_t)slot * DIM + col];
        }
        out[(size_t)n * DIM + col] = o;
    }
}

// ---------------- host launcher ----------------
extern "C" void kernel_launch(void* const* d_in, const int* in_sizes, int n_in,
                              void* d_out, int out_size) {
    const float* sequence   = (const float*)d_in[0];
    const float* input_mask = (const float*)d_in[1];
    const float* w_init     = (const float*)d_in[2];
    const float* b_init     = (const float*)d_in[3];
    const float* ln1_g      = (const float*)d_in[4];
    const float* ln1_b      = (const float*)d_in[5];
    const float* scorer_w   = (const float*)d_in[6];
    const float* scorer_b   = (const float*)d_in[7];
    const float* conv_w     = (const float*)d_in[8];
    const float* conv_b     = (const float*)d_in[9];
    const float* start      = (const float*)d_in[10];
    const float* wcell1_w   = (const float*)d_in[11];
    const float* wcell1_b   = (const float*)d_in[12];
    const float* wcell2_w   = (const float*)d_in[13];
    const float* wcell2_b   = (const float*)d_in[14];
    const float* ln2_g      = (const float*)d_in[15];
    const float* ln2_b      = (const float*)d_in[16];
    float* out = (float*)d_out;

    cudaFuncSetAttribute(mega, cudaFuncAttributeMaxDynamicSharedMemorySize, SMEM_DYN);
    mega<<<G, NT, SMEM_DYN>>>(sequence, input_mask, w_init, b_init, ln1_g, ln1_b,
                              scorer_w, scorer_b, conv_w, conv_b, start,
                              wcell1_w, wcell1_b, wcell2_w, wcell2_b, ln2_g, ln2_b, out);
}

// round 14
// speedup vs baseline: 1.1278x; 1.1278x over previous
#include <cuda_runtime.h>
#include <cuda_bf16.h>
#include <math.h>

#define NB    32
#define SL    20
#define DIM   256
#define BEAMW 4
#define G     128
#define NT    512
#define EPSC  1e-8f
#define LNEPS 1e-5f
#define NPOOL (NB * SL + 37 * NB * BEAMW)

// dynamic smem: per half (36864B): AH 9216 | AL 9216 | BH 9216 | BL 9216
#define HBASE(h) ((h) * 36864)
#define SMEM_DYN 73728

// ---------------- static device scratch ----------------
__device__ float d_pool[NPOOL * DIM];
__device__ __nv_bfloat16 d_poolh[(NPOOL + 1) * DIM];   // bf16 hi mirror (+START row)
__device__ __nv_bfloat16 d_pooll[(NPOOL + 1) * DIM];   // bf16 lo mirror
__device__ int   d_tab[2][NB * BEAMW][SL];
__device__ int   d_p[2][NB * BEAMW];
__device__ int   d_q[2][NB * BEAMW];
__device__ int   d_asrc[2][128 * 3];       // laster/last/cur: >=0 pool row, -1 start, -2 zero
__device__ float d_cpart[3 * 128 * 256];   // conv partials ks3
__device__ float d_i1[2 * 128 * 1024];     // cell1 partials ks2
__device__ float d_c2[4 * 128 * 1024];     // cell2 partials ks4
__device__ float d_rs[128], d_ss[128];
__device__ float d_bscore[NB * BEAMW];
__device__ __nv_bfloat16 d_w1h[512 * 1024],  d_w1l[512 * 1024];
__device__ __nv_bfloat16 d_w2h[1024 * 1024], d_w2l[1024 * 1024];
__device__ __nv_bfloat16 d_wch[768 * 256],   d_wcl[768 * 256];
__device__ volatile unsigned g_flags[G];
__device__ volatile unsigned g_rel;

// ---------------- flag-array grid barrier (R12 design: block0 detects) ----------------
__device__ __forceinline__ void gbar(unsigned& ep) {
    __syncthreads();
    int tid = threadIdx.x;
    int bid = blockIdx.x;
    if (tid == 0) {
        __threadfence();
        g_flags[bid] = ep;
    }
    if (bid == 0) {
        if (tid < G) {
            while (g_flags[tid] < ep) { }
        }
        __syncthreads();
        if (tid == 0) {
            __threadfence();
            g_rel = ep;
        }
    } else {
        if (tid == 0) {
            while (g_rel < ep) { }
            __threadfence();
        }
    }
    __syncthreads();
    ep++;
}

// ---------------- helpers ----------------
__device__ __forceinline__ float geluf(float x) {
    return 0.5f * x * (1.0f + erff(x * 0.7071067811865476f));
}
__device__ __forceinline__ float sigmoidf_(float x) {
    return 1.0f / (1.0f + expf(-x));
}
__device__ __forceinline__ float halfReduceSum(float v, float* sbuf) {
    int tid = threadIdx.x;
    #pragma unroll
    for (int o = 16; o > 0; o >>= 1) v += __shfl_down_sync(0xffffffffu, v, o);
    if ((tid & 31) == 0) sbuf[tid >> 5] = v;
    __syncthreads();
    int h = tid >> 8;
    float r = 0.f;
    #pragma unroll
    for (int w = 0; w < 8; w++) r += sbuf[h * 8 + w];
    __syncthreads();
    return r;
}
__device__ __forceinline__ unsigned smem_u32(const void* p) {
    unsigned a;
    asm("{ .reg .u64 t; cvta.to.shared.u64 t, %1; cvt.u32.u64 %0, t; }" : "=r"(a) : "l"(p));
    return a;
}
__device__ __forceinline__ void cvt2(float a, float b, unsigned& h, unsigned& l) {
    __nv_bfloat162 hh = __floats2bfloat162_rn(a, b);
    __nv_bfloat162 ll = __floats2bfloat162_rn(a - __bfloat162float(hh.x),
                                              b - __bfloat162float(hh.y));
    h = *reinterpret_cast<unsigned*>(&hh);
    l = *reinterpret_cast<unsigned*>(&ll);
}
// per-element hi/lo write to the pool mirrors
__device__ __forceinline__ void mirror_write(int row, int col, float v) {
    __nv_bfloat16 hh = __float2bfloat16(v);
    d_poolh[(size_t)row * DIM + col] = hh;
    d_pooll[(size_t)row * DIM + col] = __float2bfloat16(v - __bfloat162float(hh));
}

#define LDM_X4(r, addr) \
    asm volatile("ldmatrix.sync.aligned.m8n8.x4.shared.b16 {%0,%1,%2,%3}, [%4];" \
        : "=r"((r)[0]), "=r"((r)[1]), "=r"((r)[2]), "=r"((r)[3]) : "r"(addr))
#define LDM_X4T(r, addr) \
    asm volatile("ldmatrix.sync.aligned.m8n8.x4.trans.shared.b16 {%0,%1,%2,%3}, [%4];" \
        : "=r"((r)[0]), "=r"((r)[1]), "=r"((r)[2]), "=r"((r)[3]) : "r"(addr))
#define MMA16816(d, a, b0, b1) \
    asm volatile("mma.sync.aligned.m16n8k16.row.col.f32.bf16.bf16.f32 " \
        "{%0,%1,%2,%3},{%4,%5,%6,%7},{%8,%9},{%0,%1,%2,%3};" \
        : "+f"((d)[0]), "+f"((d)[1]), "+f"((d)[2]), "+f"((d)[3]) \
        : "r"((a)[0]), "r"((a)[1]), "r"((a)[2]), "r"((a)[3]), "r"(b0), "r"(b1))
#define CPA16(dst, src) \
    asm volatile("cp.async.cg.shared.global [%0], [%1], 16;" :: "r"(dst), "l"(src) : "memory")
#define CPA_COMMIT() asm volatile("cp.async.commit_group;" ::: "memory")
#define CPA_WAIT()   asm volatile("cp.async.wait_group 0;" ::: "memory")

// ---------------- mma GEMM job: 64 rows x 64 cols x K256 ----------------
// Two 256-thread halves: half h processes chunks {h, 2+h}; results combined at end.
// Warp tile 16 rows x 32 cols: 8 warps per half cover 64x64.
// amode 0: A rows from bf16 pool mirrors via dsc[seg=ks]; amode 1: A = gelu(i1_0+i1_1+gb).
__device__ void gemm_mma(int amode, int ri, int ks,
                         const int* __restrict__ dsc,
                         const float* __restrict__ gb,
                         const __nv_bfloat16* __restrict__ bH,
                         const __nv_bfloat16* __restrict__ bL, int Nw, int coloff,
                         float* __restrict__ C, int ldc,
                         char* dsb, unsigned sbase) {
    int tid = threadIdx.x;
    int half = tid >> 8;
    int htid = tid & 255;
    int lane = tid & 31;
    int w8 = htid >> 5;                    // 0..7
    int mg = w8 >> 1, ng = w8 & 1;         // rows mg*16, cols ng*32
    float acc[16];
    #pragma unroll
    for (int i = 0; i < 16; i++) acc[i] = 0.f;

    int r = htid >> 2;          // 0..63 staging row
    int q = htid & 3;           // col quarter (16 elems)
    int m = ri * 64 + r;
    unsigned hb = sbase + HBASE(half);
    char*    hp = dsb + HBASE(half);
    unsigned stOff = (unsigned)(r * 72 + q * 16) * 2;    // bytes
    unsigned aOff = ((mg * 16 + (lane & 15)) * 72 + (lane >> 4) * 8) * 2;
    unsigned bOff = ((lane & 15) * 72 + ng * 32 + (lane >> 4) * 8) * 2;

    int id = 0;
    if (amode == 0) {
        id = dsc[m * 3 + ks];
        if (id == -1) id = NPOOL;          // START mirror row
    }

    int kbase = ks * 256;
    #pragma unroll
    for (int step = 0; step < 2; step++) {
        int c = step * 2 + half;
        int kc = c * 64 + q * 16;          // col within 256-seg
        // ---- stage B (cp.async) ----
        {
            size_t so = (size_t)(kbase + c * 64 + r) * Nw + coloff + q * 16;
            CPA16(hb + 18432 + stOff,      bH + so);
            CPA16(hb + 18432 + stOff + 16, bH + so + 8);
            CPA16(hb + 27648 + stOff,      bL + so);
            CPA16(hb + 27648 + stOff + 16, bL + so + 8);
            CPA_COMMIT();
        }
        // ---- stage A ----
        if (amode == 0) {
            if (id >= 0) {
                const uint4* sh = (const uint4*)(d_poolh + (size_t)id * 256 + kc);
                const uint4* sl = (const uint4*)(d_pooll + (size_t)id * 256 + kc);
                uint4 h0 = sh[0], h1 = sh[1], l0 = sl[0], l1 = sl[1];
                *(uint4*)(hp + stOff)            = h0;
                *(uint4*)(hp + stOff + 16)       = h1;
                *(uint4*)(hp + 9216 + stOff)     = l0;
                *(uint4*)(hp + 9216 + stOff + 16) = l1;
            } else {
                uint4 z = make_uint4(0, 0, 0, 0);
                *(uint4*)(hp + stOff)             = z;
                *(uint4*)(hp + stOff + 16)        = z;
                *(uint4*)(hp + 9216 + stOff)      = z;
                *(uint4*)(hp + 9216 + stOff + 16) = z;
            }
        } else {
            int kt = kbase + kc;
            const float* pa = d_i1 + (size_t)m * 1024 + kt;
            float x[16];
            #pragma unroll
            for (int e = 0; e < 4; e++) {
                float4 a0 = *(const float4*)(pa + 4 * e);
                float4 b0 = *(const float4*)(pa + 131072 + 4 * e);
                float4 g0 = *(const float4*)(gb + kt + 4 * e);
                x[4 * e + 0] = geluf(a0.x + b0.x + g0.x);
                x[4 * e + 1] = geluf(a0.y + b0.y + g0.y);
                x[4 * e + 2] = geluf(a0.z + b0.z + g0.z);
                x[4 * e + 3] = geluf(a0.w + b0.w + g0.w);
            }
            uint4 H0, H1, L0, L1;
            cvt2(x[0], x[1], H0.x, L0.x);   cvt2(x[2], x[3], H0.y, L0.y);
            cvt2(x[4], x[5], H0.z, L0.z);   cvt2(x[6], x[7], H0.w, L0.w);
            cvt2(x[8], x[9], H1.x, L1.x);   cvt2(x[10], x[11], H1.y, L1.y);
            cvt2(x[12], x[13], H1.z, L1.z); cvt2(x[14], x[15], H1.w, L1.w);
            *(uint4*)(hp + stOff)             = H0;
            *(uint4*)(hp + stOff + 16)        = H1;
            *(uint4*)(hp + 9216 + stOff)      = L0;
            *(uint4*)(hp + 9216 + stOff + 16) = L1;
        }
        CPA_WAIT();
        __syncthreads();

        unsigned aH = hb + aOff;
        unsigned aL = hb + 9216 + aOff;
        unsigned bHs = hb + 18432 + bOff;
        unsigned bLs = hb + 27648 + bOff;
        #pragma unroll
        for (int kk = 0; kk < 4; kk++) {
            unsigned ah[4], al[4], bh0[4], bh1[4], bl0[4], bl1[4];
            LDM_X4(ah, aH + kk * 32);
            LDM_X4(al, aL + kk * 32);
            LDM_X4T(bh0, bHs + kk * 2304);
            LDM_X4T(bh1, bHs + kk * 2304 + 32);
            LDM_X4T(bl0, bLs + kk * 2304);
            LDM_X4T(bl1, bLs + kk * 2304 + 32);
            MMA16816(acc,      ah, bh0[0], bh0[1]);
            MMA16816(acc,      al, bh0[0], bh0[1]);
            MMA16816(acc,      ah, bl0[0], bl0[1]);
            MMA16816(acc + 4,  ah, bh0[2], bh0[3]);
            MMA16816(acc + 4,  al, bh0[2], bh0[3]);
            MMA16816(acc + 4,  ah, bl0[2], bl0[3]);
            MMA16816(acc + 8,  ah, bh1[0], bh1[1]);
            MMA16816(acc + 8,  al, bh1[0], bh1[1]);
            MMA16816(acc + 8,  ah, bl1[0], bl1[1]);
            MMA16816(acc + 12, ah, bh1[2], bh1[3]);
            MMA16816(acc + 12, al, bh1[2], bh1[3]);
            MMA16816(acc + 12, ah, bl1[2], bl1[3]);
        }
        __syncthreads();
    }

    // ---- cross-half combine (half1 -> smem; half0 adds + writes C) ----
    float* xb = (float*)(dsb + HBASE(1));
    if (half == 1) {
        #pragma unroll
        for (int j = 0; j < 16; j++) xb[htid * 16 + j] = acc[j];
    }
    __syncthreads();
    if (half == 0) {
        #pragma unroll
        for (int j = 0; j < 16; j++) acc[j] += xb[htid * 16 + j];
        int rw = mg * 16 + (lane >> 2);
        #pragma unroll
        for (int g = 0; g < 4; g++) {
            int cw = ng * 32 + g * 8 + (lane & 3) * 2;
            *(float2*)(C + (size_t)rw * ldc + cw)       = make_float2(acc[4 * g], acc[4 * g + 1]);
            *(float2*)(C + (size_t)(rw + 8) * ldc + cw) = make_float2(acc[4 * g + 2], acc[4 * g + 3]);
        }
    }
    __syncthreads();
}

// ---------------- the persistent mega kernel ----------------
__global__ void __launch_bounds__(NT, 1)
mega(const float* __restrict__ sequence, const float* __restrict__ input_mask,
     const float* __restrict__ w_init, const float* __restrict__ b_init,
     const float* __restrict__ ln1_g, const float* __restrict__ ln1_b,
     const float* __restrict__ scorer_w, const float* __restrict__ scorer_b,
     const float* __restrict__ conv_w, const float* __restrict__ conv_b,
     const float* __restrict__ start,
     const float* __restrict__ wcell1_w, const float* __restrict__ wcell1_b,
     const float* __restrict__ wcell2_w, const float* __restrict__ wcell2_b,
     const float* __restrict__ ln2_g, const float* __restrict__ ln2_b,
     float* __restrict__ out) {
    extern __shared__ char dsb[];
    unsigned sbase = smem_u32(dsb);
    __shared__ float sred[16];
    __shared__ int   sparK[BEAMW], swrpos[BEAMW], swrval[BEAMW];

    int tid = threadIdx.x;
    int bid = blockIdx.x;
    int h   = tid >> 8;
    int col = tid & 255;
    unsigned ep = 1;

    // ---- init 0: elementwise weight conversion to bf16 hi/lo ----
    {
        const int T1 = 512 * 1024, T2 = T1 + 1024 * 1024, T3 = T2 + 768 * 256;
        for (int idx = bid * NT + tid; idx < T3; idx += G * NT) {
            float v; __nv_bfloat16* ph; __nv_bfloat16* pl; int o;
            if (idx < T1)      { v = wcell1_w[idx];      ph = d_w1h; pl = d_w1l; o = idx; }
            else if (idx < T2) { o = idx - T1; v = wcell2_w[o]; ph = d_w2h; pl = d_w2l; }
            else               { o = idx - T2; v = conv_w[o];   ph = d_wch; pl = d_wcl; }
            __nv_bfloat16 hh = __float2bfloat16(v);
            ph[o] = hh;
            pl[o] = __float2bfloat16(v - __bfloat162float(hh));
        }
    }
    // ---- init 1: pool tokens = LN1(...) (+ mirrors); START mirror row ----
    {
        float* sX = (float*)dsb;
        for (int job = bid; job < (NB * SL) / 2; job += G) {
            int row = job * 2 + h;
            sX[h * 256 + col] = sequence[(size_t)row * DIM + col];
            __syncthreads();
            float acc = 0.f;
            for (int i = 0; i < DIM; i++)
                acc += sX[h * 256 + i] * w_init[i * DIM + col];
            float y = acc + b_init[col];
            float s1 = halfReduceSum(y, sred);
            float s2 = halfReduceSum(y * y, sred);
            float m = s1 * (1.0f / DIM);
            float var = s2 * (1.0f / DIM) - m * m;
            float v = (y - m) * rsqrtf(var + LNEPS) * ln1_g[col] + ln1_b[col];
            d_pool[(size_t)row * DIM + col] = v;
            mirror_write(row, col, v);
            __syncthreads();
        }
        if (bid == G - 1 && tid < 768) { d_asrc[0][tid] = 0; d_asrc[1][tid] = 0; }
        if (bid == 0 && tid < 256) mirror_write(NPOOL, tid, start[tid]);
    }
    gbar(ep);

    // ---- init 2: stack tables + first descriptors (K=1) ----
    if (bid < NB && tid == 0) {
        int n = bid;
        d_tab[0][n * BEAMW][0] = n * SL + 0;
        d_tab[0][n * BEAMW][1] = n * SL + 1;
        int p = (input_mask[n * SL + 1] > 0.5f) ? 1 : 0;
        d_p[0][n * BEAMW] = p;
        d_q[0][n * BEAMW] = 0;
        d_asrc[0][n * 3 + 0] = (p >= 1) ? (n * SL + 0) : -1;
        d_asrc[0][n * 3 + 1] = n * SL + p;
        d_asrc[0][n * 3 + 2] = n * SL + 2;
    }
    gbar(ep);

    int K = 1, buf = 0;
    for (int t = 2; t <= 2 * SL - 2; t++) {
        int newK = (2 * K < BEAMW) ? 2 * K : BEAMW;
        int nb2 = buf ^ 1;
        const int* dsc = d_asrc[buf];

        // ---- P1: cell1 (ks2: 64 jobs) + conv (ks3: 24 jobs) ----
        if (bid < 88) {
            if (bid < 64) {
                int ks = bid & 1, ct = (bid >> 1) & 15, ri = bid >> 5;
                gemm_mma(0, ri, ks, dsc, nullptr,
                         d_w1h, d_w1l, 1024, ct * 64,
                         d_i1 + (size_t)ks * 131072 + (size_t)ri * 64 * 1024 + ct * 64,
                         1024, dsb, sbase);
            } else {
                int j = bid - 64;
                int ks = j % 3, r2 = j / 3;
                int ct = r2 & 3, ri = r2 >> 2;
                gemm_mma(0, ri, ks, dsc, nullptr,
                         d_wch, d_wcl, 256, ct * 64,
                         d_cpart + (size_t)ks * 32768 + (size_t)ri * 64 * 256 + ct * 64,
                         256, dsb, sbase);
            }
        }
        gbar(ep);

        // ---- P2: cell2 (ks4: 128 jobs) + distributed scores tail ----
        {
            int ks = bid & 3, ct = (bid >> 2) & 15, ri = bid >> 6;
            gemm_mma(1, ri, ks, nullptr, wcell1_b,
                     d_w2h, d_w2l, 1024, ct * 64,
                     d_c2 + (size_t)ks * 131072 + (size_t)ri * 64 * 1024 + ct * 64,
                     1024, dsb, sbase);
        }
        if (bid < 64) {
            int m = 2 * bid + h;
            int valid = (m < NB * K);
            int mm = valid ? m : 0;
            float s = d_cpart[mm * 256 + col]
                    + d_cpart[32768 + mm * 256 + col]
                    + d_cpart[65536 + mm * 256 + col];
            float y = valid ? geluf(s + conv_b[col]) * scorer_w[col] : 0.f;
            float dot = halfReduceSum(y, sred);
            if (col == 0 && valid) {
                int n = mm / K, k = mm % K;
                float dec = sigmoidf_(dot + scorer_b[0]);
                int p = d_p[buf][n * BEAMW + k];
                int q = d_q[buf][n * BEAMW + k];
                float lp  = (p >= 1) ? 1.0f : 0.0f;
                float cmf = (q < SL - 2) ? input_mask[n * SL + 2 + q] : 0.0f;
                float bz  = ((lp == 0.0f) && (cmf == 0.0f)) ? 1.0f : 0.0f;
                float rs = cmf * dec + (1.0f - cmf);
                rs = lp * rs; rs = bz + (1.0f - bz) * rs; rs = logf(rs + EPSC);
                float ss = lp * (1.0f - dec) + (1.0f - lp);
                ss = cmf * ss; ss = (1.0f - bz) * ss; ss = logf(ss + EPSC);
                d_rs[mm] = rs;
                d_ss[mm] = ss;
            }
        }
        gbar(ep);

        // ---- P3: top-k + tables + descriptors (blocks 0-31) || compose (0-63) ----
        if (bid < NB) {
            int n = bid;
            if (tid == 0) {
                int C2 = 2 * K;
                float sc[8];
                for (int c = 0; c < C2; c++)
                    sc[c] = (c < K) ? d_rs[n * K + c] : d_ss[n * K + (c - K)];
                int sel[BEAMW];
                if (C2 <= BEAMW) {
                    for (int s2 = 0; s2 < C2; s2++) { sel[s2] = s2; d_bscore[n * BEAMW + s2] = sc[s2]; }
                } else {
                    bool used[8];
                    for (int c = 0; c < C2; c++) used[c] = false;
                    for (int s2 = 0; s2 < BEAMW; s2++) {
                        int best = -1; float bv = 0.f;
                        for (int c = 0; c < C2; c++) {
                            if (used[c]) continue;
                            if (best < 0 || sc[c] > bv) { best = c; bv = sc[c]; }
                        }
                        used[best] = true; sel[s2] = best;
                        d_bscore[n * BEAMW + s2] = bv;
                    }
                }
                for (int s2 = 0; s2 < newK; s2++) {
                    int c = sel[s2];
                    int isred = (c < K);
                    int k = isred ? c : (c - K);
                    int p = d_p[buf][n * BEAMW + k];
                    int q = d_q[buf][n * BEAMW + k];
                    int lp = (p >= 1);
                    float cmf = (q < SL - 2) ? input_mask[n * SL + 2 + q] : 0.0f;
                    int cm = (cmf > 0.5f);
                    int wr_pos = -1, newp = p, newq = q, wr_val = 0;
                    if (isred) {
                        if (lp) { wr_pos = p - 1; newp = p - 1;
                                  wr_val = NB * SL + (t - 2) * (NB * BEAMW) + n * BEAMW + k; }
                    } else {
                        newq = q + 1;
                        if (cm) { wr_pos = p + 1; newp = p + 1; wr_val = n * SL + 2 + q; }
                    }
                    sparK[s2] = k; swrpos[s2] = wr_pos; swrval[s2] = wr_val;
                    d_p[nb2][n * BEAMW + s2] = newp;
                    d_q[nb2][n * BEAMW + s2] = newq;
                    const int* ot = d_tab[buf][n * BEAMW + k];
                    int laster = -1;
                    if (newp >= 1) {
                        int d = newp - 1;
                        laster = (d == wr_pos) ? wr_val : ot[d];
                    }
                    int lastv = (newp == wr_pos) ? wr_val : ot[newp];
                    int curv  = (newq < SL - 2) ? (n * SL + 2 + newq) : -2;
                    int m2 = n * newK + s2;
                    d_asrc[nb2][m2 * 3 + 0] = laster;
                    d_asrc[nb2][m2 * 3 + 1] = lastv;
                    d_asrc[nb2][m2 * 3 + 2] = curv;
                }
            }
            __syncthreads();
            if (tid < newK * SL) {
                int s2 = tid / SL, d = tid % SL;
                int pk = sparK[s2];
                int v = d_tab[buf][n * BEAMW + pk][d];
                if (d == swrpos[s2]) v = swrval[s2];
                d_tab[nb2][n * BEAMW + s2][d] = v;
            }
            __syncthreads();
        }
        if (bid < 64) {
            int m = 2 * bid + h;
            int valid = (m < NB * K);
            int mm = valid ? m : 0;
            const float* c0 = d_c2 + (size_t)mm * 1024;
            float seg[4];
            #pragma unroll
            for (int sg = 0; sg < 4; sg++) {
                seg[sg] = c0[sg * 256 + col]
                        + c0[131072 + sg * 256 + col]
                        + c0[262144 + sg * 256 + col]
                        + c0[393216 + sg * 256 + col]
                        + wcell2_b[sg * 256 + col];
            }
            int id1 = dsc[mm * 3 + 0];
            int id2 = dsc[mm * 3 + 1];
            float c1 = (id1 >= 0) ? d_pool[(size_t)id1 * DIM + col] : start[col];
            float c2v = d_pool[(size_t)id2 * DIM + col];
            float x = sigmoidf_(seg[0]) * c1
                    + sigmoidf_(seg[1]) * c2v
                    + sigmoidf_(seg[2]) * seg[3];
            float xm = valid ? x : 0.f;
            float s1 = halfReduceSum(xm, sred);
            float s2 = halfReduceSum(xm * xm, sred);
            if (valid) {
                float mn = s1 * (1.0f / DIM);
                float var = s2 * (1.0f / DIM) - mn * mn;
                int n = mm / K, k = mm % K;
                int rid = NB * SL + (t - 2) * (NB * BEAMW) + n * BEAMW + k;
                float v = (x - mn) * rsqrtf(var + LNEPS) * ln2_g[col] + ln2_b[col];
                d_pool[(size_t)rid * DIM + col] = v;
                mirror_write(rid, col, v);
            }
        }
        gbar(ep);
        buf ^= 1;
        K = newK;
    }

    // ---- final: softmax over beam scores, weighted top-of-stack sum ----
    if (bid < NB && h == 0) {
        int n = bid;
        float sc[BEAMW];
        float mx = -1e30f;
        #pragma unroll
        for (int k = 0; k < BEAMW; k++) { sc[k] = d_bscore[n * BEAMW + k]; mx = fmaxf(mx, sc[k]); }
        float e[BEAMW], sum = 0.f;
        #pragma unroll
        for (int k = 0; k < BEAMW; k++) { e[k] = expf(sc[k] - mx); sum += e[k]; }
        float o = 0.f;
        #pragma unroll
        for (int k = 0; k < BEAMW; k++) {
            int p = d_p[buf][n * BEAMW + k];
            int slot = d_tab[buf][n * BEAMW + k][p];
            o += (e[k] / sum) * d_pool[(size_t)slot * DIM + col];
        }
        out[(size_t)n * DIM + col] = o;
    }
}

// ---------------- host launcher ----------------
extern "C" void kernel_launch(void* const* d_in, const int* in_sizes, int n_in,
                              void* d_out, int out_size) {
    const float* sequence   = (const float*)d_in[0];
    const float* input_mask = (const float*)d_in[1];
    const float* w_init     = (const float*)d_in[2];
    const float* b_init     = (const float*)d_in[3];
    const float* ln1_g      = (const float*)d_in[4];
    const float* ln1_b      = (const float*)d_in[5];
    const float* scorer_w   = (const float*)d_in[6];
    const float* scorer_b   = (const float*)d_in[7];
    const float* conv_w     = (const float*)d_in[8];
    const float* conv_b     = (const float*)d_in[9];
    const float* start      = (const float*)d_in[10];
    const float* wcell1_w   = (const float*)d_in[11];
    const float* wcell1_b   = (const float*)d_in[12];
    const float* wcell2_w   = (const float*)d_in[13];
    const float* wcell2_b   = (const float*)d_in[14];
    const float* ln2_g      = (const float*)d_in[15];
    const float* ln2_b      = (const float*)d_in[16];
    float* out = (float*)d_out;

    cudaFuncSetAttribute(mega, cudaFuncAttributeMaxDynamicSharedMemorySize, SMEM_DYN);
    mega<<<G, NT, SMEM_DYN>>>(sequence, input_mask, w_init, b_init, ln1_g, ln1_b,
                              scorer_w, scorer_b, conv_w, conv_b, start,
                              wcell1_w, wcell1_b, wcell2_w, wcell2_b, ln2_g, ln2_b, out);
}

// round 15
// speedup vs baseline: 1.1315x; 1.0033x over previous
#include <cuda_runtime.h>
#include <cuda_bf16.h>
#include <math.h>

#define NB    32
#define SL    20
#define DIM   256
#define BEAMW 4
#define G     256
#define NT    256
#define EPSC  1e-8f
#define LNEPS 1e-5f
#define NPOOL (NB * SL + 37 * NB * BEAMW)

// per-buffer (36864B): AH 9216 | AL 9216 | BH 9216 | BL 9216 ; two buffers
#define OAH(b) ((b) * 36864)
#define OAL(b) ((b) * 36864 + 9216)
#define OBH(b) ((b) * 36864 + 18432)
#define OBL(b) ((b) * 36864 + 27648)
#define SMEM_DYN 73728

// ---------------- static device scratch ----------------
__device__ float d_pool[NPOOL * DIM];
__device__ __nv_bfloat16 d_poolh[(NPOOL + 1) * DIM];   // bf16 hi mirror (+START row)
__device__ __nv_bfloat16 d_pooll[(NPOOL + 1) * DIM];
__device__ int   d_tab[2][NB * BEAMW][SL];
__device__ int   d_p[2][NB * BEAMW];
__device__ int   d_q[2][NB * BEAMW];
__device__ int   d_asrc[2][128 * 3];       // laster/last/cur: >=0 pool row, -1 start, -2 zero
__device__ float d_cpart[6 * 128 * 256];   // conv partials ks6 (K128)
__device__ float d_i1[4 * 128 * 1024];     // cell1 partials ks4 (K128)
__device__ float d_c2[8 * 128 * 1024];     // cell2 partials ks8 (K128)
__device__ float d_rs[128], d_ss[128];
__device__ float d_bscore[NB * BEAMW];
__device__ __nv_bfloat16 d_w1h[512 * 1024],  d_w1l[512 * 1024];
__device__ __nv_bfloat16 d_w2h[1024 * 1024], d_w2l[1024 * 1024];
__device__ __nv_bfloat16 d_wch[768 * 256],   d_wcl[768 * 256];
__device__ volatile unsigned g_flags[G];
__device__ volatile unsigned g_rel;
__device__ unsigned g_epbase = 0;          // persists across graph replays

// ---------------- replay-safe flag-array grid barrier ----------------
__device__ __forceinline__ void gbar(unsigned& ep) {
    __syncthreads();
    int tid = threadIdx.x;
    int bid = blockIdx.x;
    if (tid == 0) {
        __threadfence();
        g_flags[bid] = ep;
    }
    if (bid == 0) {
        while (g_flags[tid] < ep) { }      // NT==G/1? tid<256==G, one flag each
        __syncthreads();
        if (tid == 0) {
            __threadfence();
            g_rel = ep;
        }
    } else {
        if (tid == 0) {
            while (g_rel < ep) { }
            __threadfence();
        }
    }
    __syncthreads();
    ep++;
}

// ---------------- helpers ----------------
__device__ __forceinline__ float geluf(float x) {
    return 0.5f * x * (1.0f + erff(x * 0.7071067811865476f));
}
__device__ __forceinline__ float sigmoidf_(float x) {
    return 1.0f / (1.0f + expf(-x));
}
__device__ __forceinline__ float blockReduceSum(float v, float* sb) {
    int tid = threadIdx.x;
    #pragma unroll
    for (int o = 16; o > 0; o >>= 1) v += __shfl_down_sync(0xffffffffu, v, o);
    if ((tid & 31) == 0) sb[tid >> 5] = v;
    __syncthreads();
    if (tid == 0) {
        float r = 0.f;
        #pragma unroll
        for (int w = 0; w < 8; w++) r += sb[w];
        sb[0] = r;
    }
    __syncthreads();
    float r = sb[0];
    __syncthreads();
    return r;
}
__device__ __forceinline__ unsigned smem_u32(const void* p) {
    unsigned a;
    asm("{ .reg .u64 t; cvta.to.shared.u64 t, %1; cvt.u32.u64 %0, t; }" : "=r"(a) : "l"(p));
    return a;
}
__device__ __forceinline__ void cvt2(float a, float b, unsigned& h, unsigned& l) {
    __nv_bfloat162 hh = __floats2bfloat162_rn(a, b);
    __nv_bfloat162 ll = __floats2bfloat162_rn(a - __bfloat162float(hh.x),
                                              b - __bfloat162float(hh.y));
    h = *reinterpret_cast<unsigned*>(&hh);
    l = *reinterpret_cast<unsigned*>(&ll);
}
__device__ __forceinline__ void mirror_write(int row, int col, float v) {
    __nv_bfloat16 hh = __float2bfloat16(v);
    d_poolh[(size_t)row * DIM + col] = hh;
    d_pooll[(size_t)row * DIM + col] = __float2bfloat16(v - __bfloat162float(hh));
}

#define LDM_X4(r, addr) \
    asm volatile("ldmatrix.sync.aligned.m8n8.x4.shared.b16 {%0,%1,%2,%3}, [%4];" \
        : "=r"((r)[0]), "=r"((r)[1]), "=r"((r)[2]), "=r"((r)[3]) : "r"(addr))
#define LDM_X4T(r, addr) \
    asm volatile("ldmatrix.sync.aligned.m8n8.x4.trans.shared.b16 {%0,%1,%2,%3}, [%4];" \
        : "=r"((r)[0]), "=r"((r)[1]), "=r"((r)[2]), "=r"((r)[3]) : "r"(addr))
#define MMA16816(d, a, b0, b1) \
    asm volatile("mma.sync.aligned.m16n8k16.row.col.f32.bf16.bf16.f32 " \
        "{%0,%1,%2,%3},{%4,%5,%6,%7},{%8,%9},{%0,%1,%2,%3};" \
        : "+f"((d)[0]), "+f"((d)[1]), "+f"((d)[2]), "+f"((d)[3]) \
        : "r"((a)[0]), "r"((a)[1]), "r"((a)[2]), "r"((a)[3]), "r"(b0), "r"(b1))
#define CPA16(dst, src) \
    asm volatile("cp.async.cg.shared.global [%0], [%1], 16;" :: "r"(dst), "l"(src) : "memory")
#define CPA_COMMIT() asm volatile("cp.async.commit_group;" ::: "memory")
#define CPA_WAITG(n) asm volatile("cp.async.wait_group %0;" :: "n"(n) : "memory")

// ---------------- pipelined mma GEMM job: 64 rows x 64 cols x K128 (2 chunks) ----
// 8 warps: mg=w>>1 rows mg*16..+15; ng=w&1 cols ng*32..+31.
// amode 0: A rows from bf16 pool mirrors via dsc (seg constant per job);
// amode 1: A = gelu(sum 4 i1 slabs + gb).
__device__ void gemm_mma(int amode, int ri, int kbase,
                         const int* __restrict__ dsc,
                         const float* __restrict__ gb,
                         const __nv_bfloat16* __restrict__ bH,
                         const __nv_bfloat16* __restrict__ bL, int Nw, int coloff,
                         float* __restrict__ C, int ldc,
                         char* dsb, unsigned sbase) {
    int tid = threadIdx.x;
    int lane = tid & 31, w = tid >> 5;
    int mg = w >> 1, ng = w & 1;
    float acc[16];
    #pragma unroll
    for (int i = 0; i < 16; i++) acc[i] = 0.f;

    int r = tid >> 2;            // 0..63
    int q = tid & 3;             // 16-col quarter
    int m = ri * 64 + r;
    unsigned stOff = (unsigned)(r * 72 + q * 16) * 2;
    unsigned aOff = ((mg * 16 + (lane & 15)) * 72 + (lane >> 4) * 8) * 2;
    unsigned bOff = ((lane & 15) * 72 + ng * 32 + (lane >> 4) * 8) * 2;

    int id = 0;
    if (amode == 0) {
        id = dsc[m * 3 + (kbase >> 8)];
        if (id == -1) id = NPOOL;
    }

    uint4 A0[4], A1[4];
    auto stageA = [&](int c, uint4* R) {
        if (amode == 0) {
            if (id >= 0) {
                int kc = (kbase & 255) + c * 64 + q * 16;
                const uint4* sh = (const uint4*)(d_poolh + (size_t)id * 256 + kc);
                const uint4* sl = (const uint4*)(d_pooll + (size_t)id * 256 + kc);
                R[0] = sh[0]; R[1] = sh[1]; R[2] = sl[0]; R[3] = sl[1];
            } else {
                R[0] = R[1] = R[2] = R[3] = make_uint4(0, 0, 0, 0);
            }
        } else {
            int kt = kbase + c * 64 + q * 16;
            const float* pa = d_i1 + (size_t)m * 1024 + kt;
            float x[16];
            #pragma unroll
            for (int e = 0; e < 4; e++) {
                float4 a0 = *(const float4*)(pa + 4 * e);
                float4 b0 = *(const float4*)(pa + 131072 + 4 * e);
                float4 c0 = *(const float4*)(pa + 262144 + 4 * e);
                float4 d0 = *(const float4*)(pa + 393216 + 4 * e);
                float4 g0 = *(const float4*)(gb + kt + 4 * e);
                x[4 * e + 0] = geluf(a0.x + b0.x + c0.x + d0.x + g0.x);
                x[4 * e + 1] = geluf(a0.y + b0.y + c0.y + d0.y + g0.y);
                x[4 * e + 2] = geluf(a0.z + b0.z + c0.z + d0.z + g0.z);
                x[4 * e + 3] = geluf(a0.w + b0.w + c0.w + d0.w + g0.w);
            }
            uint4 H0, H1, L0, L1;
            cvt2(x[0], x[1], H0.x, L0.x);   cvt2(x[2], x[3], H0.y, L0.y);
            cvt2(x[4], x[5], H0.z, L0.z);   cvt2(x[6], x[7], H0.w, L0.w);
            cvt2(x[8], x[9], H1.x, L1.x);   cvt2(x[10], x[11], H1.y, L1.y);
            cvt2(x[12], x[13], H1.z, L1.z); cvt2(x[14], x[15], H1.w, L1.w);
            R[0] = H0; R[1] = H1; R[2] = L0; R[3] = L1;
        }
    };
    auto storeA = [&](const uint4* R, int b) {
        *(uint4*)(dsb + OAH(b) + stOff)      = R[0];
        *(uint4*)(dsb + OAH(b) + stOff + 16) = R[1];
        *(uint4*)(dsb + OAL(b) + stOff)      = R[2];
        *(uint4*)(dsb + OAL(b) + stOff + 16) = R[3];
    };
    auto cpB = [&](int c, int b) {
        size_t so = (size_t)(kbase + c * 64 + r) * Nw + coloff + q * 16;
        CPA16(sbase + OBH(b) + stOff,      bH + so);
        CPA16(sbase + OBH(b) + stOff + 16, bH + so + 8);
        CPA16(sbase + OBL(b) + stOff,      bL + so);
        CPA16(sbase + OBL(b) + stOff + 16, bL + so + 8);
        CPA_COMMIT();
    };

    // prologue: stage both chunks' loads up front
    stageA(0, A0);
    cpB(0, 0);
    storeA(A0, 0);
    stageA(1, A1);       // gmem loads for chunk 1 in flight during chunk 0 mma
    cpB(1, 1);
    CPA_WAITG(1);        // chunk-0 B complete; chunk-1 group may stay in flight
    __syncthreads();

    #pragma unroll
    for (int c = 0; c < 2; c++) {
        unsigned aH = sbase + OAH(c) + aOff;
        unsigned aL = sbase + OAL(c) + aOff;
        unsigned bHs = sbase + OBH(c) + bOff;
        unsigned bLs = sbase + OBL(c) + bOff;
        #pragma unroll
        for (int kk = 0; kk < 4; kk++) {
            unsigned ah[4], al[4], bh0[4], bh1[4], bl0[4], bl1[4];
            LDM_X4(ah, aH + kk * 32);
            LDM_X4(al, aL + kk * 32);
            LDM_X4T(bh0, bHs + kk * 2304);
            LDM_X4T(bh1, bHs + kk * 2304 + 32);
            LDM_X4T(bl0, bLs + kk * 2304);
            LDM_X4T(bl1, bLs + kk * 2304 + 32);
            MMA16816(acc,      ah, bh0[0], bh0[1]);
            MMA16816(acc,      al, bh0[0], bh0[1]);
            MMA16816(acc,      ah, bl0[0], bl0[1]);
            MMA16816(acc + 4,  ah, bh0[2], bh0[3]);
            MMA16816(acc + 4,  al, bh0[2], bh0[3]);
            MMA16816(acc + 4,  ah, bl0[2], bl0[3]);
            MMA16816(acc + 8,  ah, bh1[0], bh1[1]);
            MMA16816(acc + 8,  al, bh1[0], bh1[1]);
            MMA16816(acc + 8,  ah, bl1[0], bl1[1]);
            MMA16816(acc + 12, ah, bh1[2], bh1[3]);
            MMA16816(acc + 12, al, bh1[2], bh1[3]);
            MMA16816(acc + 12, ah, bl1[2], bl1[3]);
        }
        if (c == 0) {
            storeA(A1, 1);
            CPA_WAITG(0);
            __syncthreads();
        }
    }

    int rw = mg * 16 + (lane >> 2);
    #pragma unroll
    for (int g = 0; g < 4; g++) {
        int cw = ng * 32 + g * 8 + (lane & 3) * 2;
        *(float2*)(C + (size_t)rw * ldc + cw)       = make_float2(acc[4 * g], acc[4 * g + 1]);
        *(float2*)(C + (size_t)(rw + 8) * ldc + cw) = make_float2(acc[4 * g + 2], acc[4 * g + 3]);
    }
    __syncthreads();
}

// ---------------- the persistent mega kernel ----------------
__global__ void __launch_bounds__(NT, 2)
mega(const float* __restrict__ sequence, const float* __restrict__ input_mask,
     const float* __restrict__ w_init, const float* __restrict__ b_init,
     const float* __restrict__ ln1_g, const float* __restrict__ ln1_b,
     const float* __restrict__ scorer_w, const float* __restrict__ scorer_b,
     const float* __restrict__ conv_w, const float* __restrict__ conv_b,
     const float* __restrict__ start,
     const float* __restrict__ wcell1_w, const float* __restrict__ wcell1_b,
     const float* __restrict__ wcell2_w, const float* __restrict__ wcell2_b,
     const float* __restrict__ ln2_g, const float* __restrict__ ln2_b,
     float* __restrict__ out) {
    extern __shared__ char dsb[];
    unsigned sbase = smem_u32(dsb);
    __shared__ float sred[8];
    __shared__ int   sparK[BEAMW], swrpos[BEAMW], swrval[BEAMW];

    int tid = threadIdx.x;
    int bid = blockIdx.x;
    unsigned ep = g_epbase + 1;   // replay-safe epoch base

    // ---- init 0: weight conversion ----
    {
        const int T1 = 512 * 1024, T2 = T1 + 1024 * 1024, T3 = T2 + 768 * 256;
        for (int idx = bid * NT + tid; idx < T3; idx += G * NT) {
            float v; __nv_bfloat16* ph; __nv_bfloat16* pl; int o;
            if (idx < T1)      { v = wcell1_w[idx];      ph = d_w1h; pl = d_w1l; o = idx; }
            else if (idx < T2) { o = idx - T1; v = wcell2_w[o]; ph = d_w2h; pl = d_w2l; }
            else               { o = idx - T2; v = conv_w[o];   ph = d_wch; pl = d_wcl; }
            __nv_bfloat16 hh = __float2bfloat16(v);
            ph[o] = hh;
            pl[o] = __float2bfloat16(v - __bfloat162float(hh));
        }
    }
    // ---- init 1: LN1 tokens -> pool + mirrors; START mirror ----
    {
        float* sX = (float*)dsb;
        for (int row = bid; row < NB * SL; row += G) {
            sX[tid] = sequence[(size_t)row * DIM + tid];
            __syncthreads();
            float acc = 0.f;
            for (int i = 0; i < DIM; i++)
                acc += sX[i] * w_init[i * DIM + tid];
            float y = acc + b_init[tid];
            float s1 = blockReduceSum(y, sred);
            float s2 = blockReduceSum(y * y, sred);
            float mn = s1 * (1.0f / DIM);
            float var = s2 * (1.0f / DIM) - mn * mn;
            float v = (y - mn) * rsqrtf(var + LNEPS) * ln1_g[tid] + ln1_b[tid];
            d_pool[(size_t)row * DIM + tid] = v;
            mirror_write(row, tid, v);
            __syncthreads();
        }
        if (bid == G - 1) {
            for (int i = tid; i < 768; i += NT) { d_asrc[0][i] = 0; d_asrc[1][i] = 0; }
        }
        if (bid == 0) mirror_write(NPOOL, tid, start[tid]);
    }
    gbar(ep);

    // ---- init 2: stack tables + first descriptors (K=1) ----
    if (bid < NB && tid == 0) {
        int n = bid;
        d_tab[0][n * BEAMW][0] = n * SL + 0;
        d_tab[0][n * BEAMW][1] = n * SL + 1;
        int p = (input_mask[n * SL + 1] > 0.5f) ? 1 : 0;
        d_p[0][n * BEAMW] = p;
        d_q[0][n * BEAMW] = 0;
        d_asrc[0][n * 3 + 0] = (p >= 1) ? (n * SL + 0) : -1;
        d_asrc[0][n * 3 + 1] = n * SL + p;
        d_asrc[0][n * 3 + 2] = n * SL + 2;
    }
    gbar(ep);

    int K = 1, buf = 0;
    for (int t = 2; t <= 2 * SL - 2; t++) {
        int newK = (2 * K < BEAMW) ? 2 * K : BEAMW;
        int nb2 = buf ^ 1;
        const int* dsc = d_asrc[buf];

        // ---- P1: cell1 (ks4: 128 jobs) + conv (ks6: 48 jobs) ----
        if (bid < 176) {
            if (bid < 128) {
                int ks = bid & 3, ct = (bid >> 2) & 15, ri = bid >> 6;
                gemm_mma(0, ri, ks * 128, dsc, nullptr,
                         d_w1h, d_w1l, 1024, ct * 64,
                         d_i1 + (size_t)ks * 131072 + (size_t)ri * 64 * 1024 + ct * 64,
                         1024, dsb, sbase);
            } else {
                int j = bid - 128;
                int ks = j % 6, r2 = j / 6;
                int ct = r2 & 3, ri = r2 >> 2;
                gemm_mma(0, ri, ks * 128, dsc, nullptr,
                         d_wch, d_wcl, 256, ct * 64,
                         d_cpart + (size_t)ks * 32768 + (size_t)ri * 64 * 256 + ct * 64,
                         256, dsb, sbase);
            }
        }
        gbar(ep);

        // ---- P2: cell2 (ks8: 256 jobs) + scores tail (blocks 0-127) ----
        {
            int ks = bid & 7, ct = (bid >> 3) & 15, ri = bid >> 7;
            gemm_mma(1, ri, ks * 128, nullptr, wcell1_b,
                     d_w2h, d_w2l, 1024, ct * 64,
                     d_c2 + (size_t)ks * 131072 + (size_t)ri * 64 * 1024 + ct * 64,
                     1024, dsb, sbase);
        }
        if (bid < 128) {
            int m = bid;
            int valid = (m < NB * K);
            int mm = valid ? m : 0;
            float s = 0.f;
            #pragma unroll
            for (int ks = 0; ks < 6; ks++)
                s += d_cpart[ks * 32768 + mm * 256 + tid];
            float y = valid ? geluf(s + conv_b[tid]) * scorer_w[tid] : 0.f;
            float dot = blockReduceSum(y, sred);
            if (tid == 0 && valid) {
                int n = mm / K, k = mm % K;
                float dec = sigmoidf_(dot + scorer_b[0]);
                int p = d_p[buf][n * BEAMW + k];
                int q = d_q[buf][n * BEAMW + k];
                float lp  = (p >= 1) ? 1.0f : 0.0f;
                float cmf = (q < SL - 2) ? input_mask[n * SL + 2 + q] : 0.0f;
                float bz  = ((lp == 0.0f) && (cmf == 0.0f)) ? 1.0f : 0.0f;
                float rs = cmf * dec + (1.0f - cmf);
                rs = lp * rs; rs = bz + (1.0f - bz) * rs; rs = logf(rs + EPSC);
                float ss = lp * (1.0f - dec) + (1.0f - lp);
                ss = cmf * ss; ss = (1.0f - bz) * ss; ss = logf(ss + EPSC);
                d_rs[mm] = rs;
                d_ss[mm] = ss;
            }
        }
        gbar(ep);

        // ---- P3: top-k/tables/descriptors (blocks 0-31) + compose (blocks 0-127) ----
        if (bid < NB) {
            int n = bid;
            if (tid == 0) {
                int C2 = 2 * K;
                float sc[8];
                for (int c = 0; c < C2; c++)
                    sc[c] = (c < K) ? d_rs[n * K + c] : d_ss[n * K + (c - K)];
                int sel[BEAMW];
                if (C2 <= BEAMW) {
                    for (int s2 = 0; s2 < C2; s2++) { sel[s2] = s2; d_bscore[n * BEAMW + s2] = sc[s2]; }
                } else {
                    bool used[8];
                    for (int c = 0; c < C2; c++) used[c] = false;
                    for (int s2 = 0; s2 < BEAMW; s2++) {
                        int best = -1; float bv = 0.f;
                        for (int c = 0; c < C2; c++) {
                            if (used[c]) continue;
                            if (best < 0 || sc[c] > bv) { best = c; bv = sc[c]; }
                        }
                        used[best] = true; sel[s2] = best;
                        d_bscore[n * BEAMW + s2] = bv;
                    }
                }
                for (int s2 = 0; s2 < newK; s2++) {
                    int c = sel[s2];
                    int isred = (c < K);
                    int k = isred ? c : (c - K);
                    int p = d_p[buf][n * BEAMW + k];
                    int q = d_q[buf][n * BEAMW + k];
                    int lp = (p >= 1);
                    float cmf = (q < SL - 2) ? input_mask[n * SL + 2 + q] : 0.0f;
                    int cm = (cmf > 0.5f);
                    int wr_pos = -1, newp = p, newq = q, wr_val = 0;
                    if (isred) {
                        if (lp) { wr_pos = p - 1; newp = p - 1;
                                  wr_val = NB * SL + (t - 2) * (NB * BEAMW) + n * BEAMW + k; }
                    } else {
                        newq = q + 1;
                        if (cm) { wr_pos = p + 1; newp = p + 1; wr_val = n * SL + 2 + q; }
                    }
                    sparK[s2] = k; swrpos[s2] = wr_pos; swrval[s2] = wr_val;
                    d_p[nb2][n * BEAMW + s2] = newp;
                    d_q[nb2][n * BEAMW + s2] = newq;
                    const int* ot = d_tab[buf][n * BEAMW + k];
                    int laster = -1;
                    if (newp >= 1) {
                        int d = newp - 1;
                        laster = (d == wr_pos) ? wr_val : ot[d];
                    }
                    int lastv = (newp == wr_pos) ? wr_val : ot[newp];
                    int curv  = (newq < SL - 2) ? (n * SL + 2 + newq) : -2;
                    int m2 = n * newK + s2;
                    d_asrc[nb2][m2 * 3 + 0] = laster;
                    d_asrc[nb2][m2 * 3 + 1] = lastv;
                    d_asrc[nb2][m2 * 3 + 2] = curv;
                }
            }
            __syncthreads();
            if (tid < newK * SL) {
                int s2 = tid / SL, d = tid % SL;
                int pk = sparK[s2];
                int v = d_tab[buf][n * BEAMW + pk][d];
                if (d == swrpos[s2]) v = swrval[s2];
                d_tab[nb2][n * BEAMW + s2][d] = v;
            }
            __syncthreads();
        }
        if (bid < 128) {
            int m = bid;
            int valid = (m < NB * K);
            int mm = valid ? m : 0;
            const float* c0 = d_c2 + (size_t)mm * 1024;
            float seg[4];
            #pragma unroll
            for (int sg = 0; sg < 4; sg++) {
                float v = wcell2_b[sg * 256 + tid];
                #pragma unroll
                for (int ks = 0; ks < 8; ks++)
                    v += c0[ks * 131072 + sg * 256 + tid];
                seg[sg] = v;
            }
            int id1 = dsc[mm * 3 + 0];
            int id2 = dsc[mm * 3 + 1];
            float c1 = (id1 >= 0) ? d_pool[(size_t)id1 * DIM + tid] : start[tid];
            float c2v = d_pool[(size_t)id2 * DIM + tid];
            float x = sigmoidf_(seg[0]) * c1
                    + sigmoidf_(seg[1]) * c2v
                    + sigmoidf_(seg[2]) * seg[3];
            float xm = valid ? x : 0.f;
            float s1 = blockReduceSum(xm, sred);
            float s2 = blockReduceSum(xm * xm, sred);
            if (valid) {
                float mn = s1 * (1.0f / DIM);
                float var = s2 * (1.0f / DIM) - mn * mn;
                int n = mm / K, k = mm % K;
                int rid = NB * SL + (t - 2) * (NB * BEAMW) + n * BEAMW + k;
                float v = (x - mn) * rsqrtf(var + LNEPS) * ln2_g[tid] + ln2_b[tid];
                d_pool[(size_t)rid * DIM + tid] = v;
                mirror_write(rid, tid, v);
            }
        }
        gbar(ep);
        buf ^= 1;
        K = newK;
    }

    // ---- final: softmax over beam scores, weighted top-of-stack sum ----
    if (bid < NB) {
        int n = bid;
        float sc[BEAMW];
        float mx = -1e30f;
        #pragma unroll
        for (int k = 0; k < BEAMW; k++) { sc[k] = d_bscore[n * BEAMW + k]; mx = fmaxf(mx, sc[k]); }
        float e[BEAMW], sum = 0.f;
        #pragma unroll
        for (int k = 0; k < BEAMW; k++) { e[k] = expf(sc[k] - mx); sum += e[k]; }
        float o = 0.f;
        #pragma unroll
        for (int k = 0; k < BEAMW; k++) {
            int p = d_p[buf][n * BEAMW + k];
            int slot = d_tab[buf][n * BEAMW + k][p];
            o += (e[k] / sum) * d_pool[(size_t)slot * DIM + tid];
        }
        out[(size_t)n * DIM + tid] = o;
    }

    // advance persistent epoch base for the next (replayed) launch
    if (bid == 0 && tid == 0) g_epbase = ep - 1;
}

// ---------------- host launcher ----------------
extern "C" void kernel_launch(void* const* d_in, const int* in_sizes, int n_in,
                              void* d_out, int out_size) {
    const float* sequence   = (const float*)d_in[0];
    const float* input_mask = (const float*)d_in[1];
    const float* w_init     = (const float*)d_in[2];
    const float* b_init     = (const float*)d_in[3];
    const float* ln1_g      = (const float*)d_in[4];
    const float* ln1_b      = (const float*)d_in[5];
    const float* scorer_w   = (const float*)d_in[6];
    const float* scorer_b   = (const float*)d_in[7];
    const float* conv_w     = (const float*)d_in[8];
    const float* conv_b     = (const float*)d_in[9];
    const float* start      = (const float*)d_in[10];
    const float* wcell1_w   = (const float*)d_in[11];
    const float* wcell1_b   = (const float*)d_in[12];
    const float* wcell2_w   = (const float*)d_in[13];
    const float* wcell2_b   = (const float*)d_in[14];
    const float* ln2_g      = (const float*)d_in[15];
    const float* ln2_b      = (const float*)d_in[16];
    float* out = (float*)d_out;

    cudaFuncSetAttribute(mega, cudaFuncAttributeMaxDynamicSharedMemorySize, SMEM_DYN);
    mega<<<G, NT, SMEM_DYN>>>(sequence, input_mask, w_init, b_init, ln1_g, ln1_b,
                              scorer_w, scorer_b, conv_w, conv_b, start,
                              wcell1_w, wcell1_b, wcell2_w, wcell2_b, ln2_g, ln2_b, out);
}